// round 8
// baseline (speedup 1.0000x reference)
#include <cuda_runtime.h>
#include <cuda_fp16.h>
#include <cstdint>

// SoftPixelCNN R8: fp16 feature table + occupancy squeeze.
// vs R7: (1) __launch_bounds__(128,9) -> 56-reg cap, 36 warps/SM;
//        (2) w8v prefetch dropped (load at group start) to free regs;
//        (3) offset-8 accumulated feature-paired: 2 FFMA2 replace 4 FFMA/k.
// Structure otherwise: 2 vertices/warp half-split, fp32 weights in SMEM read
// as (w,w+1) LDS.128 pairs, f32x2 offset-pair accumulators, cross-group
// feature-gather prefetch.

typedef unsigned long long u64;

#define MAXV 50176
__device__ uint2 g_hfeats[MAXV * 16];   // V x 64 halves, as uint2 (4 halves each)

__global__ __launch_bounds__(256)
void cvt_kernel(const float* __restrict__ feats, int n4)  // n4 = V*16 uint2 elems
{
    const int i = blockIdx.x * blockDim.x + threadIdx.x;
    if (i >= n4) return;
    const float4 v = ((const float4*)feats)[i];
    const __half2 a = __floats2half2_rn(v.x, v.y);
    const __half2 b = __floats2half2_rn(v.z, v.w);
    uint2 r;
    r.x = *(const unsigned*)&a;
    r.y = *(const unsigned*)&b;
    g_hfeats[i] = r;
}

__global__ __launch_bounds__(128, 9)
void spcnn_kernel(const float* __restrict__ coords,   // (V,4)
                  const int*   __restrict__ nbr,      // (V,32)
                  const float* __restrict__ ls,       // (1,)
                  float*       __restrict__ out,      // (V,576)
                  int V)
{
    const int warp = threadIdx.x >> 5;
    const int lane = threadIdx.x & 31;
    const int hb   = lane >> 4;          // which vertex this half owns
    const int hl   = lane & 15;
    const int vbase = (blockIdx.x * 4 + warp) * 2;

    struct WarpScratch {
        float w07[2][32][8];   // 2048 B: weights w0..w7 per (vertex, k)
        float w8a[2][32];      // 256 B : w8 per (vertex, k)
        int   ib [2][32];      // 256 B : neighbor indices
    };
    __shared__ __align__(16) WarpScratch ws[4];
    WarpScratch& S = ws[warp];

    if (vbase >= V) return;
    const float g = 10.0f * ls[0];

    // ---------------- Phase 1: each lane fills weights for both vertices -------
    #pragma unroll
    for (int s = 0; s < 2; ++s) {
        const int v = vbase + s;
        if (v >= V) break;
        const int idx = nbr[v * 32 + lane];
        const float4 cv = ((const float4*)coords)[v];
        const float4 cn = ((const float4*)coords)[idx];
        const float dx = cv.x - cn.x;
        const float dy = cv.y - cn.y;
        const float dz = cv.z - cn.z;
        const float dw = cv.w - cn.w;
        const float base = dx*dx + dy*dy + dz*dz + dw*dw;
        const float b1 = base + 1.0f;

        // OFFSETS (verified R1): o0=0 o1=-y o2=-x o3=-z o4=-w o5=+w o6=+z o7=+x o8=+y
        const float w0 = __expf(-g * base);
        const float w1 = __expf(-g * (b1 - 2.0f * dy));
        const float w2 = __expf(-g * (b1 - 2.0f * dx));
        const float w3 = __expf(-g * (b1 - 2.0f * dz));
        const float w4 = __expf(-g * (b1 - 2.0f * dw));
        const float w5 = __expf(-g * (b1 + 2.0f * dw));
        const float w6 = __expf(-g * (b1 + 2.0f * dz));
        const float w7 = __expf(-g * (b1 + 2.0f * dx));
        const float w8 = __expf(-g * (b1 + 2.0f * dy));

        float* wr = S.w07[s][lane];
        ((float4*)wr)[0] = make_float4(w0, w1, w2, w3);
        ((float4*)wr)[1] = make_float4(w4, w5, w6, w7);
        S.w8a[s][lane] = w8;
        S.ib [s][lane] = idx;
    }
    __syncwarp();

    // ---------------- Phase 2: half-split sweep, gather-prefetched --------------
    const int v = vbase + hb;
    if (v >= V) return;

    u64 accp[4][4];                      // (offset 2op, 2op+1) x feature j
    u64 acc8[2];                         // offset 8, pairs (f0,f1) and (f2,f3)
    #pragma unroll
    for (int op = 0; op < 4; ++op)
        #pragma unroll
        for (int j = 0; j < 4; ++j) accp[op][j] = 0ull;
    acc8[0] = 0ull; acc8[1] = 0ull;

    const int fc = hl * 4;                              // feature column (halves)
    const __half* hfeats = (const __half*)g_hfeats + fc;

    // preload group 0: indices + gathers
    int4 i4 = *(const int4*)&S.ib[hb][0];
    uint2 hv0 = *(const uint2*)(hfeats + (size_t)i4.x * 64);
    uint2 hv1 = *(const uint2*)(hfeats + (size_t)i4.y * 64);
    uint2 hv2 = *(const uint2*)(hfeats + (size_t)i4.z * 64);
    uint2 hv3 = *(const uint2*)(hfeats + (size_t)i4.w * 64);

    #pragma unroll
    for (int gq = 0; gq < 8; ++gq) {
        const float4 w8v = *(const float4*)&S.w8a[hb][gq * 4];   // not prefetched
        const float w8s[4] = { w8v.x, w8v.y, w8v.z, w8v.w };
        const uint2 hvs[4] = { hv0, hv1, hv2, hv3 };

        // issue next group's gathers before consuming this group
        if (gq < 7) {
            i4  = *(const int4*)&S.ib[hb][(gq + 1) * 4];
            hv0 = *(const uint2*)(hfeats + (size_t)i4.x * 64);
            hv1 = *(const uint2*)(hfeats + (size_t)i4.y * 64);
            hv2 = *(const uint2*)(hfeats + (size_t)i4.z * 64);
            hv3 = *(const uint2*)(hfeats + (size_t)i4.w * 64);
        }

        #pragma unroll
        for (int t = 0; t < 4; ++t) {
            const int k = gq * 4 + t;
            const uint2 hv = hvs[t];
            const float2 f01 = __half22float2(*(const __half2*)&hv.x);
            const float2 f23 = __half22float2(*(const __half2*)&hv.y);

            const ulonglong2* wr = (const ulonglong2*)S.w07[hb][k];
            const ulonglong2 wA = wr[0];   // (w0,w1),(w2,w3)
            const ulonglong2 wB = wr[1];   // (w4,w5),(w6,w7)

            u64 fp[4];
            asm("mov.b64 %0, {%1,%1};" : "=l"(fp[0]) : "f"(f01.x));
            asm("mov.b64 %0, {%1,%1};" : "=l"(fp[1]) : "f"(f01.y));
            asm("mov.b64 %0, {%1,%1};" : "=l"(fp[2]) : "f"(f23.x));
            asm("mov.b64 %0, {%1,%1};" : "=l"(fp[3]) : "f"(f23.y));

            #pragma unroll
            for (int j = 0; j < 4; ++j) {
                asm("fma.rn.f32x2 %0, %1, %2, %0;" : "+l"(accp[0][j]) : "l"(wA.x), "l"(fp[j]));
                asm("fma.rn.f32x2 %0, %1, %2, %0;" : "+l"(accp[1][j]) : "l"(wA.y), "l"(fp[j]));
                asm("fma.rn.f32x2 %0, %1, %2, %0;" : "+l"(accp[2][j]) : "l"(wB.x), "l"(fp[j]));
                asm("fma.rn.f32x2 %0, %1, %2, %0;" : "+l"(accp[3][j]) : "l"(wB.y), "l"(fp[j]));
            }

            // offset 8, feature-paired: 2 FFMA2 instead of 4 FFMA
            u64 w8p, p01, p23;
            asm("mov.b64 %0, {%1,%1};" : "=l"(w8p) : "f"(w8s[t]));
            asm("mov.b64 %0, {%1,%2};" : "=l"(p01) : "f"(f01.x), "f"(f01.y));
            asm("mov.b64 %0, {%1,%2};" : "=l"(p23) : "f"(f23.x), "f"(f23.y));
            asm("fma.rn.f32x2 %0, %1, %2, %0;" : "+l"(acc8[0]) : "l"(w8p), "l"(p01));
            asm("fma.rn.f32x2 %0, %1, %2, %0;" : "+l"(acc8[1]) : "l"(w8p), "l"(p23));
        }
    }

    // ---------------- Epilogue: scale by 1/K, de-interleave, store --------------
    const u64 inv32p = 0x3D0000003D000000ull;   // (1/32, 1/32)
    float* orow = out + (size_t)v * 576 + fc;

    #pragma unroll
    for (int op = 0; op < 4; ++op) {
        #pragma unroll
        for (int j = 0; j < 4; ++j)
            asm("mul.rn.f32x2 %0, %0, %1;" : "+l"(accp[op][j]) : "l"(inv32p));
        const float2 e0 = *(float2*)&accp[op][0];
        const float2 e1 = *(float2*)&accp[op][1];
        const float2 e2 = *(float2*)&accp[op][2];
        const float2 e3 = *(float2*)&accp[op][3];
        *(float4*)(orow + (2 * op)     * 64) = make_float4(e0.x, e1.x, e2.x, e3.x);
        *(float4*)(orow + (2 * op + 1) * 64) = make_float4(e0.y, e1.y, e2.y, e3.y);
    }
    {
        asm("mul.rn.f32x2 %0, %0, %1;" : "+l"(acc8[0]) : "l"(inv32p));
        asm("mul.rn.f32x2 %0, %0, %1;" : "+l"(acc8[1]) : "l"(inv32p));
        const float2 a = *(float2*)&acc8[0];   // (f0,f1)
        const float2 b = *(float2*)&acc8[1];   // (f2,f3)
        *(float4*)(orow + 8 * 64) = make_float4(a.x, a.y, b.x, b.y);
    }
}

extern "C" void kernel_launch(void* const* d_in, const int* in_sizes, int n_in,
                              void* d_out, int out_size)
{
    const float* coords = (const float*)d_in[0];
    const float* feats  = (const float*)d_in[1];
    const int*   nbr    = (const int*)  d_in[3];
    const float* ls     = (const float*)d_in[4];
    float* out = (float*)d_out;

    const int V = in_sizes[0] / 4;

    // pre-pass: fp32 -> fp16 feature table in __device__ scratch
    const int n4 = V * 16;                       // uint2 elements (4 halves each)
    cvt_kernel<<<(n4 + 255) / 256, 256>>>(feats, n4);

    const int verts_per_block = 8;               // 4 warps x 2 vertices
    const int blocks = (V + verts_per_block - 1) / verts_per_block;
    spcnn_kernel<<<blocks, 128>>>(coords, nbr, ls, out, V);
}

// round 10
// speedup vs baseline: 1.1451x; 1.1451x over previous
#include <cuda_runtime.h>
#include <cuda_fp16.h>
#include <cstdint>

// SoftPixelCNN R9 (resubmit after infra failure): cp.async depth-2 gather ring.
// fp16 feature table (cvt pre-pass) + 2 vertices/warp half-split as in R7.
// Feature gathers are staged into a 4-slot SMEM ring via cp.async, 2 groups
// ahead of consumption: in-flight data costs ZERO registers, so latency
// hiding no longer fights the 64-reg budget (the R8 failure mode).
// Each lane stages and reads back only its own 8B slice -> no warp syncs in
// the loop; per-thread cp.async.wait_group visibility suffices.

typedef unsigned long long u64;

#define MAXV 50176
__device__ uint2 g_hfeats[MAXV * 16];   // V x 64 halves, as uint2 (4 halves each)

__global__ __launch_bounds__(256)
void cvt_kernel(const float* __restrict__ feats, int n4)  // n4 = V*16 uint2 elems
{
    const int i = blockIdx.x * blockDim.x + threadIdx.x;
    if (i >= n4) return;
    const float4 v = ((const float4*)feats)[i];
    const __half2 a = __floats2half2_rn(v.x, v.y);
    const __half2 b = __floats2half2_rn(v.z, v.w);
    uint2 r;
    r.x = *(const unsigned*)&a;
    r.y = *(const unsigned*)&b;
    g_hfeats[i] = r;
}

__device__ __forceinline__ unsigned smem_u32(const void* p) {
    return (unsigned)__cvta_generic_to_shared(p);
}
#define CP_ASYNC8(dst, src) \
    asm volatile("cp.async.ca.shared.global [%0], [%1], 8;" :: "r"(dst), "l"(src))
#define CP_COMMIT()  asm volatile("cp.async.commit_group;" ::: "memory")
#define CP_WAIT2()   asm volatile("cp.async.wait_group 2;" ::: "memory")

__global__ __launch_bounds__(128, 8)
void spcnn_kernel(const float* __restrict__ coords,   // (V,4)
                  const int*   __restrict__ nbr,      // (V,32)
                  const float* __restrict__ ls,       // (1,)
                  float*       __restrict__ out,      // (V,576)
                  int V)
{
    const int warp = threadIdx.x >> 5;
    const int lane = threadIdx.x & 31;
    const int hb   = lane >> 4;          // which vertex this half owns
    const int hl   = lane & 15;
    const int vbase = (blockIdx.x * 4 + warp) * 2;

    struct WarpScratch {
        float w07[2][32][8];    // 2048 B: weights w0..w7 per (vertex, k)
        float w8a[2][32];       // 256 B : w8 per (vertex, k)
        int   ib [2][32];       // 256 B : neighbor indices
        u64   fbuf[4][2][4][16];// 4096 B: ring[4] x half x row x lane (8B each)
    };
    __shared__ __align__(16) WarpScratch ws[4];
    WarpScratch& S = ws[warp];

    if (vbase >= V) return;
    const float g = 10.0f * ls[0];

    // ---------------- Phase 1: each lane fills weights for both vertices -------
    #pragma unroll
    for (int s = 0; s < 2; ++s) {
        const int v = vbase + s;
        const int idx = (v < V) ? nbr[v * 32 + lane] : 0;
        const float4 cv = ((const float4*)coords)[(v < V) ? v : 0];
        const float4 cn = ((const float4*)coords)[idx];
        const float dx = cv.x - cn.x;
        const float dy = cv.y - cn.y;
        const float dz = cv.z - cn.z;
        const float dw = cv.w - cn.w;
        const float base = dx*dx + dy*dy + dz*dz + dw*dw;
        const float b1 = base + 1.0f;

        // OFFSETS (verified R1): o0=0 o1=-y o2=-x o3=-z o4=-w o5=+w o6=+z o7=+x o8=+y
        const float w0 = __expf(-g * base);
        const float w1 = __expf(-g * (b1 - 2.0f * dy));
        const float w2 = __expf(-g * (b1 - 2.0f * dx));
        const float w3 = __expf(-g * (b1 - 2.0f * dz));
        const float w4 = __expf(-g * (b1 - 2.0f * dw));
        const float w5 = __expf(-g * (b1 + 2.0f * dw));
        const float w6 = __expf(-g * (b1 + 2.0f * dz));
        const float w7 = __expf(-g * (b1 + 2.0f * dx));
        const float w8 = __expf(-g * (b1 + 2.0f * dy));

        float* wr = S.w07[s][lane];
        ((float4*)wr)[0] = make_float4(w0, w1, w2, w3);
        ((float4*)wr)[1] = make_float4(w4, w5, w6, w7);
        S.w8a[s][lane] = w8;
        S.ib [s][lane] = idx;
    }
    __syncwarp();

    // ---------------- Phase 2: cp.async depth-2 pipeline ------------------------
    const int v = vbase + hb;

    u64 accp[4][4];                      // (offset 2op, 2op+1) x feature j
    u64 acc8[2];                         // offset 8, pairs (f0,f1) and (f2,f3)
    #pragma unroll
    for (int op = 0; op < 4; ++op)
        #pragma unroll
        for (int j = 0; j < 4; ++j) accp[op][j] = 0ull;
    acc8[0] = 0ull; acc8[1] = 0ull;

    const __half* hp = (const __half*)g_hfeats;
    const int hoff = hl * 4;             // this lane's slice, in halves (8 B)

    // stage group sg into ring slot sg&3 (4 rows x 8B per lane, per half)
    #define STAGE(sg) do {                                                    \
        const int4 si = *(const int4*)&S.ib[hb][(sg) * 4];                    \
        const unsigned d = smem_u32(&S.fbuf[(sg) & 3][hb][0][hl]);            \
        CP_ASYNC8(d,       hp + (size_t)si.x * 64 + hoff);                    \
        CP_ASYNC8(d + 128, hp + (size_t)si.y * 64 + hoff);                    \
        CP_ASYNC8(d + 256, hp + (size_t)si.z * 64 + hoff);                    \
        CP_ASYNC8(d + 384, hp + (size_t)si.w * 64 + hoff);                    \
    } while (0)

    STAGE(0); CP_COMMIT();
    STAGE(1); CP_COMMIT();

    #pragma unroll
    for (int gq = 0; gq < 8; ++gq) {
        if (gq < 6) STAGE(gq + 2);
        CP_COMMIT();                      // uniform commit (empty for tail)
        CP_WAIT2();                       // group gq now complete

        const float4 w8v = *(const float4*)&S.w8a[hb][gq * 4];
        const float w8s[4] = { w8v.x, w8v.y, w8v.z, w8v.w };
        const u64* fr = S.fbuf[gq & 3][hb][0] + hl;   // row stride = 16 u64

        #pragma unroll
        for (int t = 0; t < 4; ++t) {
            const int k = gq * 4 + t;
            const u64 hv = fr[t * 16];
            const unsigned hvx = (unsigned)hv;
            const unsigned hvy = (unsigned)(hv >> 32);
            const float2 f01 = __half22float2(*(const __half2*)&hvx);
            const float2 f23 = __half22float2(*(const __half2*)&hvy);

            const ulonglong2* wr = (const ulonglong2*)S.w07[hb][k];
            const ulonglong2 wA = wr[0];   // (w0,w1),(w2,w3)
            const ulonglong2 wB = wr[1];   // (w4,w5),(w6,w7)

            u64 fp[4];
            asm("mov.b64 %0, {%1,%1};" : "=l"(fp[0]) : "f"(f01.x));
            asm("mov.b64 %0, {%1,%1};" : "=l"(fp[1]) : "f"(f01.y));
            asm("mov.b64 %0, {%1,%1};" : "=l"(fp[2]) : "f"(f23.x));
            asm("mov.b64 %0, {%1,%1};" : "=l"(fp[3]) : "f"(f23.y));

            #pragma unroll
            for (int j = 0; j < 4; ++j) {
                asm("fma.rn.f32x2 %0, %1, %2, %0;" : "+l"(accp[0][j]) : "l"(wA.x), "l"(fp[j]));
                asm("fma.rn.f32x2 %0, %1, %2, %0;" : "+l"(accp[1][j]) : "l"(wA.y), "l"(fp[j]));
                asm("fma.rn.f32x2 %0, %1, %2, %0;" : "+l"(accp[2][j]) : "l"(wB.x), "l"(fp[j]));
                asm("fma.rn.f32x2 %0, %1, %2, %0;" : "+l"(accp[3][j]) : "l"(wB.y), "l"(fp[j]));
            }

            // offset 8, feature-paired: 2 FFMA2
            u64 w8p, p01, p23;
            asm("mov.b64 %0, {%1,%1};" : "=l"(w8p) : "f"(w8s[t]));
            asm("mov.b64 %0, {%1,%2};" : "=l"(p01) : "f"(f01.x), "f"(f01.y));
            asm("mov.b64 %0, {%1,%2};" : "=l"(p23) : "f"(f23.x), "f"(f23.y));
            asm("fma.rn.f32x2 %0, %1, %2, %0;" : "+l"(acc8[0]) : "l"(w8p), "l"(p01));
            asm("fma.rn.f32x2 %0, %1, %2, %0;" : "+l"(acc8[1]) : "l"(w8p), "l"(p23));
        }
    }
    #undef STAGE

    if (v >= V) return;

    // ---------------- Epilogue: scale by 1/K, de-interleave, store --------------
    const u64 inv32p = 0x3D0000003D000000ull;   // (1/32, 1/32)
    float* orow = out + (size_t)v * 576 + hl * 4;

    #pragma unroll
    for (int op = 0; op < 4; ++op) {
        #pragma unroll
        for (int j = 0; j < 4; ++j)
            asm("mul.rn.f32x2 %0, %0, %1;" : "+l"(accp[op][j]) : "l"(inv32p));
        const float2 e0 = *(float2*)&accp[op][0];
        const float2 e1 = *(float2*)&accp[op][1];
        const float2 e2 = *(float2*)&accp[op][2];
        const float2 e3 = *(float2*)&accp[op][3];
        *(float4*)(orow + (2 * op)     * 64) = make_float4(e0.x, e1.x, e2.x, e3.x);
        *(float4*)(orow + (2 * op + 1) * 64) = make_float4(e0.y, e1.y, e2.y, e3.y);
    }
    {
        asm("mul.rn.f32x2 %0, %0, %1;" : "+l"(acc8[0]) : "l"(inv32p));
        asm("mul.rn.f32x2 %0, %0, %1;" : "+l"(acc8[1]) : "l"(inv32p));
        const float2 a = *(float2*)&acc8[0];   // (f0,f1)
        const float2 b = *(float2*)&acc8[1];   // (f2,f3)
        *(float4*)(orow + 8 * 64) = make_float4(a.x, a.y, b.x, b.y);
    }
}

extern "C" void kernel_launch(void* const* d_in, const int* in_sizes, int n_in,
                              void* d_out, int out_size)
{
    const float* coords = (const float*)d_in[0];
    const float* feats  = (const float*)d_in[1];
    const int*   nbr    = (const int*)  d_in[3];
    const float* ls     = (const float*)d_in[4];
    float* out = (float*)d_out;

    const int V = in_sizes[0] / 4;

    // pre-pass: fp32 -> fp16 feature table in __device__ scratch
    const int n4 = V * 16;                       // uint2 elements (4 halves each)
    cvt_kernel<<<(n4 + 255) / 256, 256>>>(feats, n4);

    const int verts_per_block = 8;               // 4 warps x 2 vertices
    const int blocks = (V + verts_per_block - 1) / verts_per_block;
    spcnn_kernel<<<blocks, 128>>>(coords, nbr, ls, out, V);
}

// round 11
// speedup vs baseline: 1.2759x; 1.1142x over previous
#include <cuda_runtime.h>
#include <cuda_fp16.h>
#include <cstdint>

// SoftPixelCNN R11: R7 loop (register-prefetched fp16 gathers, 2 vertices/warp
// half-split) + bank-conflict-free weight layout.
// Key fix: weights stored k-major with the two per-vertex slabs interleaved
// 32B apart (w07[k][hb][8]) so the dual-broadcast LDS.128 (half A reads hb=0
// row, half B hb=1 row) hits disjoint banks -> 1 wavefront instead of 2.
// cvt pre-pass widened to 8 floats/thread (uint4 stores).

typedef unsigned long long u64;

#define MAXV 50176
__device__ uint2 g_hfeats[MAXV * 16];   // V x 64 halves, as uint2 (4 halves each)

__device__ __forceinline__ unsigned pack_h2(float a, float b) {
    const __half2 h = __floats2half2_rn(a, b);
    return *(const unsigned*)&h;
}

__global__ __launch_bounds__(256)
void cvt_kernel(const float* __restrict__ feats, int n8)  // n8 = V*8 (8 floats each)
{
    const int i = blockIdx.x * blockDim.x + threadIdx.x;
    if (i >= n8) return;
    const float4 a = ((const float4*)feats)[2 * i];
    const float4 b = ((const float4*)feats)[2 * i + 1];
    uint4 r;
    r.x = pack_h2(a.x, a.y);
    r.y = pack_h2(a.z, a.w);
    r.z = pack_h2(b.x, b.y);
    r.w = pack_h2(b.z, b.w);
    ((uint4*)g_hfeats)[i] = r;
}

__global__ __launch_bounds__(128, 8)
void spcnn_kernel(const float* __restrict__ coords,   // (V,4)
                  const int*   __restrict__ nbr,      // (V,32)
                  const float* __restrict__ ls,       // (1,)
                  float*       __restrict__ out,      // (V,576)
                  int V)
{
    const int warp = threadIdx.x >> 5;
    const int lane = threadIdx.x & 31;
    const int hb   = lane >> 4;          // which vertex this half owns
    const int hl   = lane & 15;
    const int vbase = (blockIdx.x * 4 + warp) * 2;

    struct WarpScratch {
        float w07[32][2][8];   // 2048 B: k-major, hb-interleaved (conflict-free)
        float w8a[2][32];      // 256 B : w8 per (vertex, k)
        int   ib [2][32];      // 256 B : neighbor indices
    };
    __shared__ __align__(16) WarpScratch ws[4];
    WarpScratch& S = ws[warp];

    if (vbase >= V) return;
    const float g = 10.0f * ls[0];

    // ---------------- Phase 1: each lane fills weights for both vertices -------
    #pragma unroll
    for (int s = 0; s < 2; ++s) {
        const int v = vbase + s;
        if (v >= V) break;
        const int idx = nbr[v * 32 + lane];
        const float4 cv = ((const float4*)coords)[v];
        const float4 cn = ((const float4*)coords)[idx];
        const float dx = cv.x - cn.x;
        const float dy = cv.y - cn.y;
        const float dz = cv.z - cn.z;
        const float dw = cv.w - cn.w;
        const float base = dx*dx + dy*dy + dz*dz + dw*dw;
        const float b1 = base + 1.0f;

        // OFFSETS (verified R1): o0=0 o1=-y o2=-x o3=-z o4=-w o5=+w o6=+z o7=+x o8=+y
        const float w0 = __expf(-g * base);
        const float w1 = __expf(-g * (b1 - 2.0f * dy));
        const float w2 = __expf(-g * (b1 - 2.0f * dx));
        const float w3 = __expf(-g * (b1 - 2.0f * dz));
        const float w4 = __expf(-g * (b1 - 2.0f * dw));
        const float w5 = __expf(-g * (b1 + 2.0f * dw));
        const float w6 = __expf(-g * (b1 + 2.0f * dz));
        const float w7 = __expf(-g * (b1 + 2.0f * dx));
        const float w8 = __expf(-g * (b1 + 2.0f * dy));

        float* wr = S.w07[lane][s];            // k = lane, slab = s
        ((float4*)wr)[0] = make_float4(w0, w1, w2, w3);
        ((float4*)wr)[1] = make_float4(w4, w5, w6, w7);
        S.w8a[s][lane] = w8;
        S.ib [s][lane] = idx;
    }
    __syncwarp();

    // ---------------- Phase 2: half-split sweep, register-prefetched gathers ----
    const int v = vbase + hb;
    if (v >= V) return;

    u64   accp[4][4];                    // (offset 2op, 2op+1) x feature j
    float acc8[4];
    #pragma unroll
    for (int op = 0; op < 4; ++op)
        #pragma unroll
        for (int j = 0; j < 4; ++j) accp[op][j] = 0ull;
    #pragma unroll
    for (int j = 0; j < 4; ++j) acc8[j] = 0.0f;

    const int fc = hl * 4;                              // feature column (halves)
    const __half* hfeats = (const __half*)g_hfeats + fc;

    // preload group 0: metadata + gathers
    int4   i4  = *(const int4*)  &S.ib [hb][0];
    float4 w8v = *(const float4*)&S.w8a[hb][0];
    uint2 hv0 = *(const uint2*)(hfeats + (size_t)i4.x * 64);
    uint2 hv1 = *(const uint2*)(hfeats + (size_t)i4.y * 64);
    uint2 hv2 = *(const uint2*)(hfeats + (size_t)i4.z * 64);
    uint2 hv3 = *(const uint2*)(hfeats + (size_t)i4.w * 64);

    #pragma unroll
    for (int gq = 0; gq < 8; ++gq) {
        const float w8s[4] = { w8v.x, w8v.y, w8v.z, w8v.w };
        const uint2 hvs[4] = { hv0, hv1, hv2, hv3 };

        // issue next group's gathers before consuming this group
        if (gq < 7) {
            i4  = *(const int4*)  &S.ib [hb][(gq + 1) * 4];
            w8v = *(const float4*)&S.w8a[hb][(gq + 1) * 4];
            hv0 = *(const uint2*)(hfeats + (size_t)i4.x * 64);
            hv1 = *(const uint2*)(hfeats + (size_t)i4.y * 64);
            hv2 = *(const uint2*)(hfeats + (size_t)i4.z * 64);
            hv3 = *(const uint2*)(hfeats + (size_t)i4.w * 64);
        }

        #pragma unroll
        for (int t = 0; t < 4; ++t) {
            const int k = gq * 4 + t;
            const uint2 hv = hvs[t];
            const float2 f01 = __half22float2(*(const __half2*)&hv.x);
            const float2 f23 = __half22float2(*(const __half2*)&hv.y);

            // conflict-free dual broadcast: hb slabs 32B apart
            const ulonglong2* wr = (const ulonglong2*)S.w07[k][hb];
            const ulonglong2 wA = wr[0];   // (w0,w1),(w2,w3)
            const ulonglong2 wB = wr[1];   // (w4,w5),(w6,w7)

            u64 fp[4];
            asm("mov.b64 %0, {%1,%1};" : "=l"(fp[0]) : "f"(f01.x));
            asm("mov.b64 %0, {%1,%1};" : "=l"(fp[1]) : "f"(f01.y));
            asm("mov.b64 %0, {%1,%1};" : "=l"(fp[2]) : "f"(f23.x));
            asm("mov.b64 %0, {%1,%1};" : "=l"(fp[3]) : "f"(f23.y));

            #pragma unroll
            for (int j = 0; j < 4; ++j) {
                asm("fma.rn.f32x2 %0, %1, %2, %0;" : "+l"(accp[0][j]) : "l"(wA.x), "l"(fp[j]));
                asm("fma.rn.f32x2 %0, %1, %2, %0;" : "+l"(accp[1][j]) : "l"(wA.y), "l"(fp[j]));
                asm("fma.rn.f32x2 %0, %1, %2, %0;" : "+l"(accp[2][j]) : "l"(wB.x), "l"(fp[j]));
                asm("fma.rn.f32x2 %0, %1, %2, %0;" : "+l"(accp[3][j]) : "l"(wB.y), "l"(fp[j]));
            }
            acc8[0] = fmaf(w8s[t], f01.x, acc8[0]);
            acc8[1] = fmaf(w8s[t], f01.y, acc8[1]);
            acc8[2] = fmaf(w8s[t], f23.x, acc8[2]);
            acc8[3] = fmaf(w8s[t], f23.y, acc8[3]);
        }
    }

    // ---------------- Epilogue: scale by 1/K, de-interleave, store --------------
    const u64   inv32p = 0x3D0000003D000000ull;   // (1/32, 1/32)
    const float inv32  = 0.03125f;
    float* orow = out + (size_t)v * 576 + fc;

    #pragma unroll
    for (int op = 0; op < 4; ++op) {
        #pragma unroll
        for (int j = 0; j < 4; ++j)
            asm("mul.rn.f32x2 %0, %0, %1;" : "+l"(accp[op][j]) : "l"(inv32p));
        const float2 e0 = *(float2*)&accp[op][0];
        const float2 e1 = *(float2*)&accp[op][1];
        const float2 e2 = *(float2*)&accp[op][2];
        const float2 e3 = *(float2*)&accp[op][3];
        *(float4*)(orow + (2 * op)     * 64) = make_float4(e0.x, e1.x, e2.x, e3.x);
        *(float4*)(orow + (2 * op + 1) * 64) = make_float4(e0.y, e1.y, e2.y, e3.y);
    }
    *(float4*)(orow + 8 * 64) = make_float4(acc8[0] * inv32, acc8[1] * inv32,
                                            acc8[2] * inv32, acc8[3] * inv32);
}

extern "C" void kernel_launch(void* const* d_in, const int* in_sizes, int n_in,
                              void* d_out, int out_size)
{
    const float* coords = (const float*)d_in[0];
    const float* feats  = (const float*)d_in[1];
    const int*   nbr    = (const int*)  d_in[3];
    const float* ls     = (const float*)d_in[4];
    float* out = (float*)d_out;

    const int V = in_sizes[0] / 4;

    // pre-pass: fp32 -> fp16 feature table (8 floats/thread, uint4 stores)
    const int n8 = V * 8;
    cvt_kernel<<<(n8 + 255) / 256, 256>>>(feats, n8);

    const int verts_per_block = 8;               // 4 warps x 2 vertices
    const int blocks = (V + verts_per_block - 1) / verts_per_block;
    spcnn_kernel<<<blocks, 128>>>(coords, nbr, ls, out, V);
}